// round 2
// baseline (speedup 1.0000x reference)
#include <cuda_runtime.h>
#include <math.h>

// Beran estimator: C=16 concepts, B=256 batch, K=8 classes, N=8192 background.
// Kernel 1: pack c_in labels (16 x int32) into 8 pair-indices (uint2) per element.
// Kernel 2: one CTA per batch row b, 512 threads, 16 contiguous n per thread.
//           Gather via 64-entry pairwise smem table (8 LDS/element).

#define CC 16
#define BB 256
#define KK 8
#define NN 8192
#define THREADS 512
#define CHUNK (NN / THREADS)   // 16
#define NWARPS (THREADS / 32)  // 16
#define NPAIRS (CC / 2)        // 8

#define ISCLOSE_TOL (1e-8f + 1e-5f)
#define EPS_GUARD 1e-13f

__device__ uint2 g_packed[NN];   // 64 KB scratch: 8 pair-bytes per element

// ---------------------------------------------------------------- pack kernel
__global__ void pack_kernel(const int* __restrict__ c_in)
{
    const int n = blockIdx.x * blockDim.x + threadIdx.x;
    if (n >= NN) return;
    const int4* cr = (const int4*)(c_in + n * CC);   // 16 ints, 64B aligned
    int4 a = cr[0], b = cr[1], c = cr[2], d = cr[3];
    unsigned lo = (unsigned)(a.x * 8 + a.y)
                | ((unsigned)(a.z * 8 + a.w) << 8)
                | ((unsigned)(b.x * 8 + b.y) << 16)
                | ((unsigned)(b.z * 8 + b.w) << 24);
    unsigned hi = (unsigned)(c.x * 8 + c.y)
                | ((unsigned)(c.z * 8 + c.w) << 8)
                | ((unsigned)(d.x * 8 + d.y) << 16)
                | ((unsigned)(d.z * 8 + d.w) << 24);
    g_packed[n] = make_uint2(lo, hi);
}

// ------------------------------------------------------------ block scan util
// Exclusive block prefix of v over all THREADS threads; also returns block
// total. wsum holds NWARPS floats. Internally synchronizes (safe for reuse).
__device__ __forceinline__ float block_scan_excl(float v, float& total,
                                                 int lane, int wid, float* wsum)
{
    __syncthreads();  // protect wsum against previous use
    float x = v;
    #pragma unroll
    for (int o = 1; o < 32; o <<= 1) {
        float y = __shfl_up_sync(0xffffffffu, x, o);
        if (lane >= o) x += y;
    }
    if (lane == 31) wsum[wid] = x;
    __syncthreads();
    if (wid == 0) {
        float s = (lane < NWARPS) ? wsum[lane] : 0.0f;
        #pragma unroll
        for (int o = 1; o < NWARPS; o <<= 1) {
            float y = __shfl_up_sync(0xffffffffu, s, o);
            if (lane >= o) s += y;
        }
        if (lane < NWARPS) wsum[lane] = s;
    }
    __syncthreads();
    total = wsum[NWARPS - 1];
    float off = (wid > 0) ? wsum[wid - 1] : 0.0f;
    return off + (x - v);   // exclusive prefix for this thread
}

// ---------------------------------------------------------------- main kernel
__global__ __launch_bounds__(THREADS, 2)
void beran_kernel(const float* __restrict__ c_p,
                  const float* __restrict__ delta_in,
                  const float* __restrict__ bandwidth,
                  float*       __restrict__ out)   // [surv_func(B*N) | surv_steps(B*N)]
{
    __shared__ float p_sh[CC * KK];          // softmax table for this b (128 floats)
    __shared__ float tab[NPAIRS * 64];       // pairwise sums: tab[p][l1*8+l2]
    __shared__ float sq_sh[CC];
    __shared__ float wsum[NWARPS];
    __shared__ float params[2];              // {inv_bw, S}

    const int b    = blockIdx.x;
    const int t    = threadIdx.x;
    const int lane = t & 31;
    const int wid  = t >> 5;
    const int n0   = t * CHUNK;

    // ---- Phase 0: softmax per concept + sumsq ----
    if (t < CC) {
        const float* row = c_p + (t * BB + b) * KK;
        float v[KK];
        float mx = -INFINITY;
        #pragma unroll
        for (int k = 0; k < KK; k++) { v[k] = row[k]; mx = fmaxf(mx, v[k]); }
        float sm = 0.0f;
        #pragma unroll
        for (int k = 0; k < KK; k++) { v[k] = expf(v[k] - mx); sm += v[k]; }
        float inv = 1.0f / sm;
        float ss = 0.0f;
        #pragma unroll
        for (int k = 0; k < KK; k++) {
            float p = v[k] * inv;
            p_sh[t * KK + k] = p;
            ss += p * p;
        }
        sq_sh[t] = ss;
    }
    __syncthreads();
    // build pairwise table: tab[p*64 + l1*8+l2] = p_sh[2p][l1] + p_sh[2p+1][l2]
    {
        const int p   = t >> 6;          // 0..7  (THREADS=512 covers all 512 entries)
        const int idx = t & 63;
        tab[t] = p_sh[(2 * p) * KK + (idx >> 3)] + p_sh[(2 * p + 1) * KK + (idx & 7)];
    }
    if (t == 0) {
        float S = (float)CC;
        #pragma unroll
        for (int c = 0; c < CC; c++) S += sq_sh[c];
        float bw = fminf(fmaxf(bandwidth[0], 0.1f), 10.0f);
        params[0] = 1.0f / bw;
        params[1] = S;
    }
    __syncthreads();
    const float inv_bw = params[0];
    const float S      = params[1];

    // ---- Phase A: weights w[n] = exp((2g - S)/bw) ----
    float buf[CHUNK];     // reused: w -> filtered_xi -> steps
    float lsum = 0.0f;
    #pragma unroll 4
    for (int i = 0; i < CHUNK; i++) {
        uint2 pk = g_packed[n0 + i];
        float g = tab[  0 + ( pk.x        & 0xFF)]
                + tab[ 64 + ((pk.x >> 8)  & 0xFF)]
                + tab[128 + ((pk.x >> 16) & 0xFF)]
                + tab[192 + ( pk.x >> 24        )]
                + tab[256 + ( pk.y        & 0xFF)]
                + tab[320 + ((pk.y >> 8)  & 0xFF)]
                + tab[384 + ((pk.y >> 16) & 0xFF)]
                + tab[448 + ( pk.y >> 24        )];
        float wv = expf((2.0f * g - S) * inv_bw);
        buf[i] = wv;
        lsum  += wv;
    }

    // ---- Scan 1: cumsum of weights; normalize; xi; filtered_xi ----
    float s_total;
    float P = block_scan_excl(lsum, s_total, lane, wid, wsum);
    const float inv_s = (s_total < EPS_GUARD) ? 0.0f : (1.0f / s_total);

    float run  = P;
    float fsum = 0.0f;
    #pragma unroll 4
    for (int i = 0; i < CHUNK; i++) {
        float shifted = run * inv_s;            // exclusive cumsum of W
        run += buf[i];
        float wc = run * inv_s;                 // inclusive cumsum of W
        bool bad = (fabsf(shifted - 1.0f) <= ISCLOSE_TOL) ||
                   (fabsf(wc      - 1.0f) <= ISCLOSE_TOL);
        if (bad) { shifted = 0.0f; wc = 0.0f; }
        float xi = logf(1.0f - shifted) - logf(1.0f - wc);
        float fx = delta_in[n0 + i] * xi;
        buf[i] = fx;
        fsum  += fx;
    }

    // ---- Scan 2: hazards cumsum; surv; steps ----
    float h_total;
    float H = block_scan_excl(fsum, h_total, lane, wid, wsum);

    float run_h = H;
    float prev  = expf(-H);   // surv[n0-1]; ==1 for thread 0 (n=0 -> 1 - surv[0])
    float ssum  = 0.0f;
    float* out_surv  = out + (size_t)b * NN;
    float* out_steps = out + (size_t)BB * NN + (size_t)b * NN;
    #pragma unroll 4
    for (int i = 0; i < CHUNK; i++) {
        run_h += buf[i];
        float sv = expf(-run_h);
        out_surv[n0 + i] = sv;
        float st = prev - sv;
        prev = sv;
        buf[i] = st;
        ssum  += st;
    }

    // ---- Reduce steps; normalize; write ----
    float s2_total;
    (void)block_scan_excl(ssum, s2_total, lane, wid, wsum);
    const float inv_s2 = (s2_total < EPS_GUARD) ? 0.0f : (1.0f / s2_total);
    #pragma unroll 4
    for (int i = 0; i < CHUNK; i++) {
        out_steps[n0 + i] = buf[i] * inv_s2;
    }
}

extern "C" void kernel_launch(void* const* d_in, const int* in_sizes, int n_in,
                              void* d_out, int out_size)
{
    const float* c_p       = (const float*)d_in[0];
    const int*   c_in      = (const int*)  d_in[1];
    const float* delta_in  = (const float*)d_in[2];
    const float* bandwidth = (const float*)d_in[3];
    float* out = (float*)d_out;

    pack_kernel<<<NN / 256, 256>>>(c_in);
    beran_kernel<<<BB, THREADS>>>(c_p, delta_in, bandwidth, out);
}

// round 11
// speedup vs baseline: 1.9684x; 1.9684x over previous
#include <cuda_runtime.h>
#include <math.h>

// Beran estimator: C=16, B=256, K=8, N=8192.
// Kernel 1: pack 16 labels -> 8 pair-indices (uint2) per element (64 KB scratch).
// Kernel 2: one CTA per batch row. 512 threads = 16 warps; warp w owns span
//           [w*512,(w+1)*512), lane-strided within span -> all global I/O
//           perfectly coalesced. Cumsums = per-round warp shuffle scans with
//           running carry + one cross-warp combine per scan.

#define CC 16
#define BB 256
#define KK 8
#define NN 8192
#define THREADS 512
#define NWARPS (THREADS / 32)   // 16
#define SPAN (NN / NWARPS)      // 512 elements per warp
#define ROUNDS (SPAN / 32)      // 16

#define ISCLOSE_TOL (1e-8f + 1e-5f)
#define EPS_GUARD 1e-13f

__device__ uint2 g_packed[NN];   // 64 KB: 8 pair-bytes per element

// ---------------------------------------------------------------- pack kernel
__global__ void pack_kernel(const int* __restrict__ c_in)
{
    const int n = blockIdx.x * blockDim.x + threadIdx.x;
    if (n >= NN) return;
    const int4* cr = (const int4*)(c_in + n * CC);
    int4 a = cr[0], b = cr[1], c = cr[2], d = cr[3];
    unsigned lo = (unsigned)(a.x * 8 + a.y)
                | ((unsigned)(a.z * 8 + a.w) << 8)
                | ((unsigned)(b.x * 8 + b.y) << 16)
                | ((unsigned)(b.z * 8 + b.w) << 24);
    unsigned hi = (unsigned)(c.x * 8 + c.y)
                | ((unsigned)(c.z * 8 + c.w) << 8)
                | ((unsigned)(d.x * 8 + d.y) << 16)
                | ((unsigned)(d.z * 8 + d.w) << 24);
    g_packed[n] = make_uint2(lo, hi);
}

// ------------------------------------------------------------------- helpers
__device__ __forceinline__ float warp_incl_scan(float x, int lane)
{
    #pragma unroll
    for (int o = 1; o < 32; o <<= 1) {
        float y = __shfl_up_sync(0xffffffffu, x, o);
        if (lane >= o) x += y;
    }
    return x;
}

// Per-warp value -> (exclusive offset among warps, block total). 2 barriers.
__device__ __forceinline__ void block_combine(float wtot, int lane, int wid,
                                              float* wsum, float& off, float& tot)
{
    if (lane == 0) wsum[wid] = wtot;
    __syncthreads();
    off = 0.0f; tot = 0.0f;
    #pragma unroll
    for (int j = 0; j < NWARPS; j++) {
        float v = wsum[j];          // broadcast LDS, conflict-free
        tot += v;
        off += (j < wid) ? v : 0.0f;
    }
    __syncthreads();                // wsum reusable afterwards
}

// ---------------------------------------------------------------- main kernel
__global__ __launch_bounds__(THREADS, 2)
void beran_kernel(const float* __restrict__ c_p,
                  const float* __restrict__ delta_in,
                  const float* __restrict__ bandwidth,
                  float*       __restrict__ out)   // [surv(B*N) | steps(B*N)]
{
    __shared__ float p_sh[CC * KK];     // softmax table (128 floats)
    __shared__ float sq_sh[CC];
    __shared__ float tab[8 * 64];       // pairwise sums tab[p][l1*8+l2]
    __shared__ float wsum[NWARPS];

    const int b     = blockIdx.x;
    const int t     = threadIdx.x;
    const int lane  = t & 31;
    const int wid   = t >> 5;
    const int nbase = wid * SPAN + lane;   // element for round i: nbase + i*32

    // ---- Phase 0: softmax per concept + sumsq ----
    if (t < CC) {
        const float* row = c_p + (t * BB + b) * KK;
        float v[KK];
        float mx = -INFINITY;
        #pragma unroll
        for (int k = 0; k < KK; k++) { v[k] = row[k]; mx = fmaxf(mx, v[k]); }
        float sm = 0.0f;
        #pragma unroll
        for (int k = 0; k < KK; k++) { v[k] = expf(v[k] - mx); sm += v[k]; }
        float inv = 1.0f / sm;
        float ss = 0.0f;
        #pragma unroll
        for (int k = 0; k < KK; k++) {
            float p = v[k] * inv;
            p_sh[t * KK + k] = p;
            ss += p * p;
        }
        sq_sh[t] = ss;
    }
    __syncthreads();

    // pairwise table (one entry per thread) + per-thread S, inv_bw
    {
        const int p   = t >> 6;
        const int idx = t & 63;
        tab[t] = p_sh[(2 * p) * KK + (idx >> 3)] + p_sh[(2 * p + 1) * KK + (idx & 7)];
    }
    float S = (float)CC;
    #pragma unroll
    for (int c = 0; c < CC; c++) S += sq_sh[c];   // broadcast LDS
    const float bwv    = fminf(fmaxf(bandwidth[0], 0.1f), 10.0f);
    const float inv_bw = 1.0f / bwv;
    __syncthreads();   // tab visible

    // ---- Phase A: weights ----
    float buf[ROUNDS];     // reused: w -> filtered_xi -> steps
    float lsum = 0.0f;
    #pragma unroll
    for (int i = 0; i < ROUNDS; i++) {
        uint2 pk = g_packed[nbase + i * 32];     // coalesced
        float g = tab[  0 + ( pk.x        & 0xFF)]
                + tab[ 64 + ((pk.x >> 8)  & 0xFF)]
                + tab[128 + ((pk.x >> 16) & 0xFF)]
                + tab[192 + ( pk.x >> 24        )]
                + tab[256 + ( pk.y        & 0xFF)]
                + tab[320 + ((pk.y >> 8)  & 0xFF)]
                + tab[384 + ((pk.y >> 16) & 0xFF)]
                + tab[448 + ( pk.y >> 24        )];
        float wv = expf((2.0f * g - S) * inv_bw);
        buf[i] = wv;
        lsum  += wv;
    }

    // warp total of weights -> block combine
    float wtot = __shfl_sync(0xffffffffu, warp_incl_scan(lsum, lane), 31);
    float w_off, s_total;
    block_combine(wtot, lane, wid, wsum, w_off, s_total);
    const float inv_s = (s_total < EPS_GUARD) ? 0.0f : (1.0f / s_total);

    // ---- Scan 1: weights cumsum -> xi -> filtered_xi ----
    float carry = 0.0f;
    float hsum  = 0.0f;
    #pragma unroll
    for (int i = 0; i < ROUNDS; i++) {
        float x    = buf[i];
        float incl = warp_incl_scan(x, lane);
        float base = w_off + carry;
        carry += __shfl_sync(0xffffffffu, incl, 31);
        float shifted = (base + incl - x) * inv_s;   // exclusive cumsum of W
        float wc      = (base + incl)     * inv_s;   // inclusive cumsum of W
        bool bad = (fabsf(shifted - 1.0f) <= ISCLOSE_TOL) ||
                   (fabsf(wc      - 1.0f) <= ISCLOSE_TOL);
        if (bad) { shifted = 0.0f; wc = 0.0f; }
        float xi = logf(1.0f - shifted) - logf(1.0f - wc);
        float fx = delta_in[nbase + i * 32] * xi;    // coalesced
        buf[i] = fx;
        hsum  += fx;
    }

    // ---- Scan 2: hazards cumsum -> surv, steps ----
    float htot = __shfl_sync(0xffffffffu, warp_incl_scan(hsum, lane), 31);
    float h_off, h_total;
    block_combine(htot, lane, wid, wsum, h_off, h_total);
    (void)h_total;

    float* out_surv  = out + (size_t)b * NN;
    float* out_steps = out + (size_t)BB * NN + (size_t)b * NN;

    float hcarry    = 0.0f;
    float prev_last = expf(-h_off);   // surv just before this warp's span (==1 for warp 0)
    float ssum      = 0.0f;
    #pragma unroll
    for (int i = 0; i < ROUNDS; i++) {
        float x    = buf[i];
        float incl = warp_incl_scan(x, lane);
        float hz   = h_off + hcarry + incl;
        hcarry += __shfl_sync(0xffffffffu, incl, 31);
        float sv = expf(-hz);
        __stcg(&out_surv[nbase + i * 32], sv);       // coalesced, streaming
        float pv = __shfl_up_sync(0xffffffffu, sv, 1);
        if (lane == 0) pv = prev_last;
        prev_last = __shfl_sync(0xffffffffu, sv, 31);
        float st = pv - sv;                          // steps[0] = 1 - surv[0] falls out
        buf[i] = st;
        ssum  += st;
    }

    // ---- steps normalization ----
    float stot = __shfl_sync(0xffffffffu, warp_incl_scan(ssum, lane), 31);
    float dummy_off, s2_total;
    block_combine(stot, lane, wid, wsum, dummy_off, s2_total);
    const float inv_s2 = (s2_total < EPS_GUARD) ? 0.0f : (1.0f / s2_total);

    #pragma unroll
    for (int i = 0; i < ROUNDS; i++) {
        __stcg(&out_steps[nbase + i * 32], buf[i] * inv_s2);   // coalesced, streaming
    }
}

extern "C" void kernel_launch(void* const* d_in, const int* in_sizes, int n_in,
                              void* d_out, int out_size)
{
    const float* c_p       = (const float*)d_in[0];
    const int*   c_in      = (const int*)  d_in[1];
    const float* delta_in  = (const float*)d_in[2];
    const float* bandwidth = (const float*)d_in[3];
    float* out = (float*)d_out;

    pack_kernel<<<NN / 256, 256>>>(c_in);
    beran_kernel<<<BB, THREADS>>>(c_p, delta_in, bandwidth, out);
}

// round 14
// speedup vs baseline: 1.9738x; 1.0028x over previous
#include <cuda_runtime.h>
#include <math.h>

// Beran estimator: C=16, B=256, K=8, N=8192.
// Kernel 1: pack 16 labels -> 4 x 12-bit quad-indices (ushort4) per element.
// Kernel 2: one CTA per batch row. 512 threads = 16 warps; warp w owns span
//           [w*512,(w+1)*512), lane-strided within span (all global I/O
//           coalesced). Gather via 4 quad tables (4096 entries each, dynamic
//           smem) -> 4 LDS/element. Cumsums = per-round warp shuffle scans.

#define CC 16
#define BB 256
#define KK 8
#define NN 8192
#define THREADS 512
#define NWARPS (THREADS / 32)   // 16
#define SPAN (NN / NWARPS)      // 512 elements per warp
#define ROUNDS (SPAN / 32)      // 16

#define QTAB_BYTES (4 * 4096 * 4)   // 64 KB dynamic smem

#define ISCLOSE_TOL (1e-8f + 1e-5f)
#define EPS_GUARD 1e-13f

__device__ ushort4 g_packedq[NN];   // 64 KB: 4 quad-indices per element

// ---------------------------------------------------------------- pack kernel
__global__ void pack_kernel(const int* __restrict__ c_in)
{
    const int n = blockIdx.x * blockDim.x + threadIdx.x;
    if (n >= NN) return;
    const int4* cr = (const int4*)(c_in + n * CC);
    int4 a = cr[0], b = cr[1], c = cr[2], d = cr[3];
    ushort4 q;
    q.x = (unsigned short)(((a.x * 8 + a.y) * 8 + a.z) * 8 + a.w);
    q.y = (unsigned short)(((b.x * 8 + b.y) * 8 + b.z) * 8 + b.w);
    q.z = (unsigned short)(((c.x * 8 + c.y) * 8 + c.z) * 8 + c.w);
    q.w = (unsigned short)(((d.x * 8 + d.y) * 8 + d.z) * 8 + d.w);
    g_packedq[n] = q;
}

// ------------------------------------------------------------------- helpers
__device__ __forceinline__ float warp_incl_scan(float x, int lane)
{
    #pragma unroll
    for (int o = 1; o < 32; o <<= 1) {
        float y = __shfl_up_sync(0xffffffffu, x, o);
        if (lane >= o) x += y;
    }
    return x;
}

// Per-warp value -> (exclusive offset among warps, block total). 2 barriers.
__device__ __forceinline__ void block_combine(float wtot, int lane, int wid,
                                              float* wsum, float& off, float& tot)
{
    if (lane == 0) wsum[wid] = wtot;
    __syncthreads();
    off = 0.0f; tot = 0.0f;
    #pragma unroll
    for (int j = 0; j < NWARPS; j++) {
        float v = wsum[j];          // broadcast LDS, conflict-free
        tot += v;
        off += (j < wid) ? v : 0.0f;
    }
    __syncthreads();                // wsum reusable afterwards
}

// ---------------------------------------------------------------- main kernel
__global__ __launch_bounds__(THREADS, 2)
void beran_kernel(const float* __restrict__ c_p,
                  const float* __restrict__ delta_in,
                  const float* __restrict__ bandwidth,
                  float*       __restrict__ out)   // [surv(B*N) | steps(B*N)]
{
    extern __shared__ float qtab[];     // 4 quad tables x 4096 floats
    __shared__ float p_sh[CC * KK];     // softmax table (128 floats)
    __shared__ float sq_sh[CC];
    __shared__ float tab[8 * 64];       // pairwise sums tab[p][l1*8+l2]
    __shared__ float wsum[NWARPS];

    const int b     = blockIdx.x;
    const int t     = threadIdx.x;
    const int lane  = t & 31;
    const int wid   = t >> 5;
    const int nbase = wid * SPAN + lane;   // element for round i: nbase + i*32

    // ---- Phase 0: softmax per concept + sumsq ----
    if (t < CC) {
        const float* row = c_p + (t * BB + b) * KK;
        float v[KK];
        float mx = -INFINITY;
        #pragma unroll
        for (int k = 0; k < KK; k++) { v[k] = row[k]; mx = fmaxf(mx, v[k]); }
        float sm = 0.0f;
        #pragma unroll
        for (int k = 0; k < KK; k++) { v[k] = expf(v[k] - mx); sm += v[k]; }
        float inv = 1.0f / sm;
        float ss = 0.0f;
        #pragma unroll
        for (int k = 0; k < KK; k++) {
            float p = v[k] * inv;
            p_sh[t * KK + k] = p;
            ss += p * p;
        }
        sq_sh[t] = ss;
    }
    __syncthreads();

    // pair tables: tab[p*64 + l1*8+l2] = p_sh[2p][l1] + p_sh[2p+1][l2]
    {
        const int p   = t >> 6;
        const int idx = t & 63;
        tab[t] = p_sh[(2 * p) * KK + (idx >> 3)] + p_sh[(2 * p + 1) * KK + (idx & 7)];
    }
    float S = (float)CC;
    #pragma unroll
    for (int c = 0; c < CC; c++) S += sq_sh[c];   // broadcast LDS
    const float bwv    = fminf(fmaxf(bandwidth[0], 0.1f), 10.0f);
    const float inv_bw = 1.0f / bwv;
    __syncthreads();   // pair tables visible

    // quad tables: qtab[q*4096 + i] = tab[q*128 + (i>>6)] + tab[q*128+64 + (i&63)]
    // i = j*512 + t: broadcast LDS on (i>>6), lane-consecutive on (i&63) & STS.
    #pragma unroll
    for (int q = 0; q < 4; q++) {
        #pragma unroll
        for (int j = 0; j < 8; j++) {
            int i = j * 512 + t;
            qtab[q * 4096 + i] = tab[q * 128 + (i >> 6)] + tab[q * 128 + 64 + (i & 63)];
        }
    }
    __syncthreads();   // quad tables visible

    // ---- Phase A: weights ----
    float buf[ROUNDS];     // reused: w -> filtered_xi -> steps
    float lsum = 0.0f;
    #pragma unroll
    for (int i = 0; i < ROUNDS; i++) {
        ushort4 pk = g_packedq[nbase + i * 32];     // coalesced 8B
        float g = qtab[          pk.x]
                + qtab[ 4096 +   pk.y]
                + qtab[ 8192 +   pk.z]
                + qtab[12288 +   pk.w];
        float wv = expf((2.0f * g - S) * inv_bw);
        buf[i] = wv;
        lsum  += wv;
    }

    // warp total of weights -> block combine
    float wtot = __shfl_sync(0xffffffffu, warp_incl_scan(lsum, lane), 31);
    float w_off, s_total;
    block_combine(wtot, lane, wid, wsum, w_off, s_total);
    const float inv_s = (s_total < EPS_GUARD) ? 0.0f : (1.0f / s_total);

    // ---- Scan 1: weights cumsum -> xi -> filtered_xi ----
    float carry = 0.0f;
    float hsum  = 0.0f;
    #pragma unroll
    for (int i = 0; i < ROUNDS; i++) {
        float x    = buf[i];
        float incl = warp_incl_scan(x, lane);
        float base = w_off + carry;
        carry += __shfl_sync(0xffffffffu, incl, 31);
        float shifted = (base + incl - x) * inv_s;   // exclusive cumsum of W
        float wc      = (base + incl)     * inv_s;   // inclusive cumsum of W
        bool bad = (fabsf(shifted - 1.0f) <= ISCLOSE_TOL) ||
                   (fabsf(wc      - 1.0f) <= ISCLOSE_TOL);
        if (bad) { shifted = 0.0f; wc = 0.0f; }
        float xi = logf(1.0f - shifted) - logf(1.0f - wc);
        float fx = delta_in[nbase + i * 32] * xi;    // coalesced
        buf[i] = fx;
        hsum  += fx;
    }

    // ---- Scan 2: hazards cumsum -> surv, steps ----
    float htot = __shfl_sync(0xffffffffu, warp_incl_scan(hsum, lane), 31);
    float h_off, h_total;
    block_combine(htot, lane, wid, wsum, h_off, h_total);
    (void)h_total;

    float* out_surv  = out + (size_t)b * NN;
    float* out_steps = out + (size_t)BB * NN + (size_t)b * NN;

    float hcarry    = 0.0f;
    float prev_last = expf(-h_off);   // surv just before this warp's span (==1 for warp 0)
    float ssum      = 0.0f;
    #pragma unroll
    for (int i = 0; i < ROUNDS; i++) {
        float x    = buf[i];
        float incl = warp_incl_scan(x, lane);
        float hz   = h_off + hcarry + incl;
        hcarry += __shfl_sync(0xffffffffu, incl, 31);
        float sv = expf(-hz);
        __stcg(&out_surv[nbase + i * 32], sv);       // coalesced, streaming
        float pv = __shfl_up_sync(0xffffffffu, sv, 1);
        if (lane == 0) pv = prev_last;
        prev_last = __shfl_sync(0xffffffffu, sv, 31);
        float st = pv - sv;                          // steps[0] = 1 - surv[0] falls out
        buf[i] = st;
        ssum  += st;
    }

    // ---- steps normalization ----
    float stot = __shfl_sync(0xffffffffu, warp_incl_scan(ssum, lane), 31);
    float dummy_off, s2_total;
    block_combine(stot, lane, wid, wsum, dummy_off, s2_total);
    const float inv_s2 = (s2_total < EPS_GUARD) ? 0.0f : (1.0f / s2_total);

    #pragma unroll
    for (int i = 0; i < ROUNDS; i++) {
        __stcg(&out_steps[nbase + i * 32], buf[i] * inv_s2);   // coalesced, streaming
    }
}

extern "C" void kernel_launch(void* const* d_in, const int* in_sizes, int n_in,
                              void* d_out, int out_size)
{
    const float* c_p       = (const float*)d_in[0];
    const int*   c_in      = (const int*)  d_in[1];
    const float* delta_in  = (const float*)d_in[2];
    const float* bandwidth = (const float*)d_in[3];
    float* out = (float*)d_out;

    cudaFuncSetAttribute(beran_kernel,
                         cudaFuncAttributeMaxDynamicSharedMemorySize, QTAB_BYTES);

    pack_kernel<<<NN / 256, 256>>>(c_in);
    beran_kernel<<<BB, THREADS, QTAB_BYTES>>>(c_p, delta_in, bandwidth, out);
}

// round 15
// speedup vs baseline: 2.4172x; 1.2247x over previous
#include <cuda_runtime.h>
#include <math.h>

// Beran estimator: C=16, B=256, K=8, N=8192.
// Kernel 1: pack 16 labels -> 8 pair-indices (uint2) per element (64 KB scratch).
// Kernel 2: one CTA per batch row. 512 threads = 16 warps; warp w owns span
//           [w*512,(w+1)*512), lane-strided within span -> all global I/O
//           coalesced. Gather via pair tables (8 LDS/elem). Hot-loop
//           transcendentals use MUFU intrinsics (__expf/__logf).

#define CC 16
#define BB 256
#define KK 8
#define NN 8192
#define THREADS 512
#define NWARPS (THREADS / 32)   // 16
#define SPAN (NN / NWARPS)      // 512 elements per warp
#define ROUNDS (SPAN / 32)      // 16

#define ISCLOSE_TOL (1e-8f + 1e-5f)
#define EPS_GUARD 1e-13f

__device__ uint2 g_packed[NN];   // 64 KB: 8 pair-bytes per element

// ---------------------------------------------------------------- pack kernel
__global__ void pack_kernel(const int* __restrict__ c_in)
{
    const int n = blockIdx.x * blockDim.x + threadIdx.x;
    if (n >= NN) return;
    const int4* cr = (const int4*)(c_in + n * CC);
    int4 a = cr[0], b = cr[1], c = cr[2], d = cr[3];
    unsigned lo = (unsigned)(a.x * 8 + a.y)
                | ((unsigned)(a.z * 8 + a.w) << 8)
                | ((unsigned)(b.x * 8 + b.y) << 16)
                | ((unsigned)(b.z * 8 + b.w) << 24);
    unsigned hi = (unsigned)(c.x * 8 + c.y)
                | ((unsigned)(c.z * 8 + c.w) << 8)
                | ((unsigned)(d.x * 8 + d.y) << 16)
                | ((unsigned)(d.z * 8 + d.w) << 24);
    g_packed[n] = make_uint2(lo, hi);
}

// ------------------------------------------------------------------- helpers
__device__ __forceinline__ float warp_incl_scan(float x, int lane)
{
    #pragma unroll
    for (int o = 1; o < 32; o <<= 1) {
        float y = __shfl_up_sync(0xffffffffu, x, o);
        if (lane >= o) x += y;
    }
    return x;
}

// Per-warp value -> (exclusive offset among warps, block total). 2 barriers.
__device__ __forceinline__ void block_combine(float wtot, int lane, int wid,
                                              float* wsum, float& off, float& tot)
{
    if (lane == 0) wsum[wid] = wtot;
    __syncthreads();
    off = 0.0f; tot = 0.0f;
    #pragma unroll
    for (int j = 0; j < NWARPS; j++) {
        float v = wsum[j];          // broadcast LDS, conflict-free
        tot += v;
        off += (j < wid) ? v : 0.0f;
    }
    __syncthreads();                // wsum reusable afterwards
}

// ---------------------------------------------------------------- main kernel
__global__ __launch_bounds__(THREADS, 2)
void beran_kernel(const float* __restrict__ c_p,
                  const float* __restrict__ delta_in,
                  const float* __restrict__ bandwidth,
                  float*       __restrict__ out)   // [surv(B*N) | steps(B*N)]
{
    __shared__ float p_sh[CC * KK];     // softmax table (128 floats)
    __shared__ float sq_sh[CC];
    __shared__ float tab[8 * 64];       // pairwise sums tab[p][l1*8+l2]
    __shared__ float wsum[NWARPS];

    const int b     = blockIdx.x;
    const int t     = threadIdx.x;
    const int lane  = t & 31;
    const int wid   = t >> 5;
    const int nbase = wid * SPAN + lane;   // element for round i: nbase + i*32

    // ---- Phase 0: softmax per concept + sumsq (precise expf; cold path) ----
    if (t < CC) {
        const float* row = c_p + (t * BB + b) * KK;
        float v[KK];
        float mx = -INFINITY;
        #pragma unroll
        for (int k = 0; k < KK; k++) { v[k] = row[k]; mx = fmaxf(mx, v[k]); }
        float sm = 0.0f;
        #pragma unroll
        for (int k = 0; k < KK; k++) { v[k] = expf(v[k] - mx); sm += v[k]; }
        float inv = 1.0f / sm;
        float ss = 0.0f;
        #pragma unroll
        for (int k = 0; k < KK; k++) {
            float p = v[k] * inv;
            p_sh[t * KK + k] = p;
            ss += p * p;
        }
        sq_sh[t] = ss;
    }
    __syncthreads();

    // pair tables (one entry per thread) + per-thread S, inv_bw
    {
        const int p   = t >> 6;
        const int idx = t & 63;
        tab[t] = p_sh[(2 * p) * KK + (idx >> 3)] + p_sh[(2 * p + 1) * KK + (idx & 7)];
    }
    float S = (float)CC;
    #pragma unroll
    for (int c = 0; c < CC; c++) S += sq_sh[c];   // broadcast LDS
    const float bwv    = fminf(fmaxf(bandwidth[0], 0.1f), 10.0f);
    const float inv_bw = 1.0f / bwv;
    __syncthreads();   // tab visible

    // ---- Phase A: weights ----
    float buf[ROUNDS];     // reused: w -> filtered_xi -> steps
    float lsum = 0.0f;
    #pragma unroll
    for (int i = 0; i < ROUNDS; i++) {
        uint2 pk = g_packed[nbase + i * 32];     // coalesced
        float g = tab[  0 + ( pk.x        & 0xFF)]
                + tab[ 64 + ((pk.x >> 8)  & 0xFF)]
                + tab[128 + ((pk.x >> 16) & 0xFF)]
                + tab[192 + ( pk.x >> 24        )]
                + tab[256 + ( pk.y        & 0xFF)]
                + tab[320 + ((pk.y >> 8)  & 0xFF)]
                + tab[384 + ((pk.y >> 16) & 0xFF)]
                + tab[448 + ( pk.y >> 24        )];
        float wv = __expf((2.0f * g - S) * inv_bw);
        buf[i] = wv;
        lsum  += wv;
    }

    // warp total of weights -> block combine
    float wtot = __shfl_sync(0xffffffffu, warp_incl_scan(lsum, lane), 31);
    float w_off, s_total;
    block_combine(wtot, lane, wid, wsum, w_off, s_total);
    const float inv_s = (s_total < EPS_GUARD) ? 0.0f : (1.0f / s_total);

    // ---- Scan 1: weights cumsum -> xi -> filtered_xi ----
    float carry = 0.0f;
    float hsum  = 0.0f;
    #pragma unroll
    for (int i = 0; i < ROUNDS; i++) {
        float x    = buf[i];
        float incl = warp_incl_scan(x, lane);
        float base = w_off + carry;
        carry += __shfl_sync(0xffffffffu, incl, 31);
        float shifted = (base + incl - x) * inv_s;   // exclusive cumsum of W
        float wc      = (base + incl)     * inv_s;   // inclusive cumsum of W
        bool bad = (fabsf(shifted - 1.0f) <= ISCLOSE_TOL) ||
                   (fabsf(wc      - 1.0f) <= ISCLOSE_TOL);
        if (bad) { shifted = 0.0f; wc = 0.0f; }
        float xi = __logf(1.0f - shifted) - __logf(1.0f - wc);
        float fx = delta_in[nbase + i * 32] * xi;    // coalesced
        buf[i] = fx;
        hsum  += fx;
    }

    // ---- Scan 2: hazards cumsum -> surv, steps ----
    float htot = __shfl_sync(0xffffffffu, warp_incl_scan(hsum, lane), 31);
    float h_off, h_total;
    block_combine(htot, lane, wid, wsum, h_off, h_total);
    (void)h_total;

    float* out_surv  = out + (size_t)b * NN;
    float* out_steps = out + (size_t)BB * NN + (size_t)b * NN;

    float hcarry    = 0.0f;
    float prev_last = __expf(-h_off);  // surv just before this warp's span (==1 for warp 0)
    float ssum      = 0.0f;
    #pragma unroll
    for (int i = 0; i < ROUNDS; i++) {
        float x    = buf[i];
        float incl = warp_incl_scan(x, lane);
        float hz   = h_off + hcarry + incl;
        hcarry += __shfl_sync(0xffffffffu, incl, 31);
        float sv = __expf(-hz);
        __stcg(&out_surv[nbase + i * 32], sv);       // coalesced, streaming
        float pv = __shfl_up_sync(0xffffffffu, sv, 1);
        if (lane == 0) pv = prev_last;
        prev_last = __shfl_sync(0xffffffffu, sv, 31);
        float st = pv - sv;                          // steps[0] = 1 - surv[0] falls out
        buf[i] = st;
        ssum  += st;
    }

    // ---- steps normalization ----
    float stot = __shfl_sync(0xffffffffu, warp_incl_scan(ssum, lane), 31);
    float dummy_off, s2_total;
    block_combine(stot, lane, wid, wsum, dummy_off, s2_total);
    const float inv_s2 = (s2_total < EPS_GUARD) ? 0.0f : (1.0f / s2_total);

    #pragma unroll
    for (int i = 0; i < ROUNDS; i++) {
        __stcg(&out_steps[nbase + i * 32], buf[i] * inv_s2);   // coalesced, streaming
    }
}

extern "C" void kernel_launch(void* const* d_in, const int* in_sizes, int n_in,
                              void* d_out, int out_size)
{
    const float* c_p       = (const float*)d_in[0];
    const int*   c_in      = (const int*)  d_in[1];
    const float* delta_in  = (const float*)d_in[2];
    const float* bandwidth = (const float*)d_in[3];
    float* out = (float*)d_out;

    pack_kernel<<<NN / 256, 256>>>(c_in);
    beran_kernel<<<BB, THREADS>>>(c_p, delta_in, bandwidth, out);
}